// round 13
// baseline (speedup 1.0000x reference)
#include <cuda_runtime.h>
#include <cuda_bf16.h>
#include <math_constants.h>

#define NF 16384
#define NP 16384
#define TPB 128
#define WPB (TPB / 32)
#define NBIN 256
#define NOFF 33
#define FQCAP 512
#define EQCAP 128
#define NBLK 1036

// Original-order triangle data (12 floats: a,b,c,n)
__device__ __align__(16) float g_tri[NF * 12];
// Canonical plane per tri (unit n with nz>=0, d = n.a); original order
__device__ float4 g_plane[NF];
// Counting-sort state
__device__ int g_bcnt[NBIN];
__device__ int g_bstart[NBIN + 1];
__device__ int g_bfill[NBIN];
__device__ float g_keys[NF];
__device__ int g_vals[NF];
// Permuted (bin-sorted-by-d) arrays
__device__ int g_poid[NF];                       // original face id
__device__ float4 g_pplane[NF];                  // (nx,ny,nz,-d)
__device__ __align__(16) float4 g_ptri4[NF * 3]; // tri data
// Bin metadata
__device__ float4 g_bmA[NBIN];   // cx,cy,cz,chordmax(inflated)
__device__ float4 g_bmB[NBIN];   // dmin, invstep, int_as_float(start), 0
__device__ int g_boff[NBIN * NOFF];
// Persistent work counter
__device__ int g_ctr;

// ---------- strict IEEE helpers (bit-stable vs reference) ----------
__device__ __forceinline__ float dot3(float x0, float x1, float x2,
                                      float y0, float y1, float y2) {
    return __fadd_rn(__fadd_rn(__fmul_rn(x0, y0), __fmul_rn(x1, y1)),
                     __fmul_rn(x2, y2));
}
__device__ __forceinline__ float sdiv(float x, float y) {
    return __fdiv_rn(x, (y == 0.0f) ? 1.0f : y);
}

// ---------- K1: triangle precompute + canonical planes ----------
__global__ void k1_tris(const float* __restrict__ vertices,
                        const int* __restrict__ faces) {
    int f = blockIdx.x * blockDim.x + threadIdx.x;
    if (f < NBIN) g_bcnt[f] = 0;
    if (f == 0) g_ctr = 0;
    if (f >= NF) return;
    int i0 = faces[f * 3 + 0];
    int i1 = faces[f * 3 + 1];
    int i2 = faces[f * 3 + 2];
    float ax = vertices[i0 * 3 + 0], ay = vertices[i0 * 3 + 1], az = vertices[i0 * 3 + 2];
    float bx = vertices[i1 * 3 + 0], by = vertices[i1 * 3 + 1], bz = vertices[i1 * 3 + 2];
    float cx = vertices[i2 * 3 + 0], cy = vertices[i2 * 3 + 1], cz = vertices[i2 * 3 + 2];
    float abx = __fsub_rn(bx, ax), aby = __fsub_rn(by, ay), abz = __fsub_rn(bz, az);
    float acx = __fsub_rn(cx, ax), acy = __fsub_rn(cy, ay), acz = __fsub_rn(cz, az);
    float nx = __fsub_rn(__fmul_rn(aby, acz), __fmul_rn(abz, acy));
    float ny = __fsub_rn(__fmul_rn(abz, acx), __fmul_rn(abx, acz));
    float nz = __fsub_rn(__fmul_rn(abx, acy), __fmul_rn(aby, acx));
    float* t = &g_tri[f * 12];
    t[0] = ax; t[1] = ay; t[2] = az;
    t[3] = bx; t[4] = by; t[5] = bz;
    t[6] = cx; t[7] = cy; t[8] = cz;
    t[9] = nx; t[10] = ny; t[11] = nz;

    float len2 = nx * nx + ny * ny + nz * nz;
    float ux = 0.0f, uy = 0.0f, uz = 0.0f, d = 0.0f;
    if (len2 > 0.0f) {
        float inv = rsqrtf(len2);
        ux = nx * inv; uy = ny * inv; uz = nz * inv;
        d = ax * ux + ay * uy + az * uz;
        if (uz < 0.0f) { ux = -ux; uy = -uy; uz = -uz; d = -d; }
    }
    g_plane[f] = make_float4(ux, uy, uz, d);
}

__device__ __forceinline__ int plane_bin(float4 pl) {
    int u = min(15, max(0, (int)((pl.x + 1.0f) * 8.0f)));
    int v = min(15, max(0, (int)((pl.y + 1.0f) * 8.0f)));
    return v * 16 + u;
}

// ---------- K2: histogram ----------
__global__ void k2_hist() {
    int f = blockIdx.x * blockDim.x + threadIdx.x;
    if (f >= NF) return;
    atomicAdd(&g_bcnt[plane_bin(g_plane[f])], 1);
}

// ---------- K3: scan (1 block, 256 threads) ----------
__global__ void k3_scan() {
    __shared__ int s[NBIN];
    int t = threadIdx.x;
    s[t] = g_bcnt[t];
    __syncthreads();
    for (int off = 1; off < NBIN; off <<= 1) {
        int v = (t >= off) ? s[t - off] : 0;
        __syncthreads();
        s[t] += v;
        __syncthreads();
    }
    g_bstart[t + 1] = s[t];
    if (t == 0) g_bstart[0] = 0;
    g_bfill[t] = 0;
}

// ---------- K4: scatter (d, face) into bin slots ----------
__global__ void k4_scatter() {
    int f = blockIdx.x * blockDim.x + threadIdx.x;
    if (f >= NF) return;
    float4 pl = g_plane[f];
    int b = plane_bin(pl);
    int pos = g_bstart[b] + atomicAdd(&g_bfill[b], 1);
    g_keys[pos] = pl.w;
    g_vals[pos] = f;
}

// ---------- K5: per-bin d-sort + permuted gather + metadata ----------
__global__ void __launch_bounds__(256) k5_sort() {
    int b = blockIdx.x;
    int t = threadIdx.x;
    int start = g_bstart[b];
    int cnt = g_bstart[b + 1] - start;

    __shared__ float sd[256];
    __shared__ int si[256];
    __shared__ float sr[256];

    sd[t] = (t < cnt) ? g_keys[start + t] : CUDART_INF_F;
    si[t] = (t < cnt) ? g_vals[start + t] : -1;
    __syncthreads();

    // bitonic sort ascending by d
    for (int k = 2; k <= 256; k <<= 1) {
        for (int j = k >> 1; j > 0; j >>= 1) {
            int ixj = t ^ j;
            if (ixj > t) {
                bool up = ((t & k) == 0);
                float a = sd[t], c = sd[ixj];
                if ((a > c) == up) {
                    sd[t] = c; sd[ixj] = a;
                    int tmp = si[t]; si[t] = si[ixj]; si[ixj] = tmp;
                }
            }
            __syncthreads();
        }
    }

    // bin-cell center direction
    float cx = ((b & 15) + 0.5f) * 0.125f - 1.0f;
    float cy = (((b >> 4) & 15) + 0.5f) * 0.125f - 1.0f;
    float cz = sqrtf(fmaxf(0.0f, 1.0f - cx * cx - cy * cy));

    // gather permuted arrays + chord distances
    float ch = 0.0f;
    if (t < cnt) {
        int f = si[t];
        int pos = start + t;
        g_poid[pos] = f;
        float4 pl = g_plane[f];
        g_pplane[pos] = make_float4(pl.x, pl.y, pl.z, -pl.w);
        const float4* src = reinterpret_cast<const float4*>(&g_tri[f * 12]);
        g_ptri4[pos * 3 + 0] = src[0];
        g_ptri4[pos * 3 + 1] = src[1];
        g_ptri4[pos * 3 + 2] = src[2];
        float dx = pl.x - cx, dy = pl.y - cy, dz = pl.z - cz;
        ch = sqrtf(dx * dx + dy * dy + dz * dz);
    }
    sr[t] = ch;
    __syncthreads();
    for (int o = 128; o > 0; o >>= 1) {
        if (t < o) sr[t] = fmaxf(sr[t], sr[t + o]);
        __syncthreads();
    }
    float chordmax = sr[0] * 1.0001f + 1e-5f;

    float dmin = (cnt > 0) ? sd[0] : 0.0f;
    float dmax = (cnt > 0) ? sd[cnt - 1] : 0.0f;
    float step = (dmax - dmin) * (1.0f / 32.0f);
    float invstep = (step > 0.0f) ? (1.0f / step) : 0.0f;

    if (t <= 32) {
        int off;
        if (t == 0) off = 0;
        else if (t >= 32 || step <= 0.0f) off = cnt;
        else {
            float thresh = dmin + t * step;
            int lo = 0, hi = cnt;
            while (lo < hi) {
                int mid = (lo + hi) >> 1;
                if (sd[mid] < thresh) lo = mid + 1; else hi = mid;
            }
            off = lo;
        }
        g_boff[b * NOFF + t] = off;
    }
    if (t == 0) {
        g_bmA[b] = make_float4(cx, cy, cz, chordmax);
        g_bmB[b] = make_float4(dmin, invstep, __int_as_float(start), 0.0f);
    }
}

// Evaluate one PERMUTED triangle exactly (bit-identical math); key uses orig id.
__device__ __forceinline__ bool eval_tri(
    int pe, float px, float py, float pz,
    unsigned long long& best_key, float& best_sd)
{
    float4 q0 = __ldg(&g_ptri4[pe * 3 + 0]);
    float4 q1 = __ldg(&g_ptri4[pe * 3 + 1]);
    float4 q2 = __ldg(&g_ptri4[pe * 3 + 2]);
    int oid = __ldg(&g_poid[pe]);
    float ax = q0.x, ay = q0.y, az = q0.z;
    float bx = q0.w, by = q1.x, bz = q1.y;
    float cx = q1.z, cy = q1.w, cz = q2.x;
    float nx = q2.y, ny = q2.z, nz = q2.w;

    float abx = __fsub_rn(bx, ax), aby = __fsub_rn(by, ay), abz = __fsub_rn(bz, az);
    float acx = __fsub_rn(cx, ax), acy = __fsub_rn(cy, ay), acz = __fsub_rn(cz, az);
    float apx = __fsub_rn(px, ax), apy = __fsub_rn(py, ay), apz = __fsub_rn(pz, az);
    float bpx = __fsub_rn(px, bx), bpy = __fsub_rn(py, by), bpz = __fsub_rn(pz, bz);
    float cpx = __fsub_rn(px, cx), cpy = __fsub_rn(py, cy), cpz = __fsub_rn(pz, cz);

    float d1 = dot3(abx, aby, abz, apx, apy, apz);
    float d2 = dot3(acx, acy, acz, apx, apy, apz);
    float d3 = dot3(abx, aby, abz, bpx, bpy, bpz);
    float d4 = dot3(acx, acy, acz, bpx, bpy, bpz);
    float d5 = dot3(abx, aby, abz, cpx, cpy, cpz);
    float d6 = dot3(acx, acy, acz, cpx, cpy, cpz);

    float va = __fsub_rn(__fmul_rn(d3, d6), __fmul_rn(d5, d4));
    float vb = __fsub_rn(__fmul_rn(d5, d2), __fmul_rn(d1, d6));
    float vc = __fsub_rn(__fmul_rn(d1, d4), __fmul_rn(d3, d2));
    float denom = __fadd_rn(__fadd_rn(va, vb), vc);
    float v = sdiv(vb, denom);
    float w = sdiv(vc, denom);

    float e43 = __fsub_rn(d4, d3);
    float e56 = __fsub_rn(d5, d6);
    float t_bc = sdiv(e43, __fadd_rn(e43, e56));
    if (va <= 0.0f && e43 >= 0.0f && e56 >= 0.0f) {
        v = __fsub_rn(1.0f, t_bc); w = t_bc;
    }
    float t_ac = sdiv(d2, __fsub_rn(d2, d6));
    if (vb <= 0.0f && d2 >= 0.0f && d6 <= 0.0f) { v = 0.0f; w = t_ac; }
    float t_ab = sdiv(d1, __fsub_rn(d1, d3));
    if (vc <= 0.0f && d1 >= 0.0f && d3 <= 0.0f) { v = t_ab; w = 0.0f; }
    if (d6 >= 0.0f && d5 <= d6) { v = 0.0f; w = 1.0f; }
    if (d3 >= 0.0f && d4 <= d3) { v = 1.0f; w = 0.0f; }
    if (d1 <= 0.0f && d2 <= 0.0f) { v = 0.0f; w = 0.0f; }

    float clx = __fadd_rn(__fadd_rn(ax, __fmul_rn(v, abx)), __fmul_rn(w, acx));
    float cly = __fadd_rn(__fadd_rn(ay, __fmul_rn(v, aby)), __fmul_rn(w, acy));
    float clz = __fadd_rn(__fadd_rn(az, __fmul_rn(v, abz)), __fmul_rn(w, acz));
    float dx = __fsub_rn(px, clx);
    float dy = __fsub_rn(py, cly);
    float dz = __fsub_rn(pz, clz);
    float dist2 = dot3(dx, dy, dz, dx, dy, dz);

    unsigned long long key =
        ((unsigned long long)__float_as_uint(dist2) << 32) | (unsigned)oid;
    if (key < best_key) {
        best_key = key;
        best_sd = dot3(dx, dy, dz, nx, ny, nz);
        return true;
    }
    return false;
}

__device__ __forceinline__ void tighten(unsigned long long best_key, float& sq) {
    float bd2 = __uint_as_float((unsigned)(best_key >> 32));
    #pragma unroll
    for (int o = 16; o > 0; o >>= 1)
        bd2 = fminf(bd2, __shfl_xor_sync(0xFFFFFFFFu, bd2, o));
    sq = fminf(sq, fmaf(sqrtf(bd2), 1.001f, 1e-6f));
}

// ---------- main: persistent warps, bin windows -> fine test -> exact eval ----
__global__ void __launch_bounds__(TPB) sdf_main(const float* __restrict__ points,
                                                float* __restrict__ out) {
    __shared__ int fq[WPB][FQCAP];
    __shared__ int eq[WPB][EQCAP];

    int w = threadIdx.x / 32;
    int lane = threadIdx.x % 32;
    unsigned lm = (1u << lane) - 1u;

    for (;;) {
        int pid;
        if (lane == 0) pid = atomicAdd(&g_ctr, 1);
        pid = __shfl_sync(0xFFFFFFFFu, pid, 0);
        if (pid >= NP) break;

        float px = points[pid * 3 + 0];
        float py = points[pid * 3 + 1];
        float pz = points[pid * 3 + 2];

        // Seed: strided vertex-a min, then exact eval of each lane's argmin
        float ub2 = CUDART_INF_F;
        int af = lane;
        #pragma unroll 4
        for (int i = 0; i < 32; i++) {
            int pe = lane + i * 512;
            float4 q0 = __ldg(&g_ptri4[pe * 3]);
            float dx = px - q0.x, dy = py - q0.y, dz = pz - q0.z;
            float d2 = fmaf(dx, dx, fmaf(dy, dy, dz * dz));
            if (d2 < ub2) { ub2 = d2; af = pe; }
        }
        unsigned long long bk = 0xFFFFFFFFFFFFFFFFull;
        float bs = 0.0f;
        eval_tri(af, px, py, pz, bk, bs);
        float sq = CUDART_INF_F;
        tighten(bk, sq);

        float plen = sqrtf(px * px + py * py + pz * pz) * 1.0001f + 1e-6f;
        int fqh = 0, fqt = 0, eqh = 0, eqt = 0;

        for (int it = 0; it < NBIN / 32; it++) {
            int b = it * 32 + lane;
            float4 mA = __ldg(&g_bmA[b]);
            float4 mB = __ldg(&g_bmB[b]);
            float s = fmaf(px, mA.x, fmaf(py, mA.y, pz * mA.z));
            float R = fmaf(mA.w, plen, sq);
            float wlo = s - R, whi = s + R;
            float fk0 = floorf((wlo - mB.x) * mB.y);
            float fk1 = floorf((whi - mB.x) * mB.y);
            fk0 = fminf(fmaxf(fk0, -2.0f), 40.0f);
            fk1 = fminf(fmaxf(fk1, -4.0f), 40.0f);
            int klo = max(0, (int)fk0 - 1);
            int khi = min(32, (int)fk1 + 2);
            int start = 0, cnt = 0;
            if (khi > klo) {
                int o0 = __ldg(&g_boff[b * NOFF + klo]);
                int o1 = __ldg(&g_boff[b * NOFF + khi]);
                start = __float_as_int(mB.z) + o0;
                cnt = o1 - o0;
            }

            // Push candidate ranges in bounded rounds, draining as we go
            while (__any_sync(0xFFFFFFFFu, cnt > 0)) {
                int take = min(cnt, 8);
                int sc = take;
                #pragma unroll
                for (int o = 1; o < 32; o <<= 1) {
                    int vv = __shfl_up_sync(0xFFFFFFFFu, sc, o);
                    if (lane >= o) sc += vv;
                }
                int total = __shfl_sync(0xFFFFFFFFu, sc, 31);
                int ofs = sc - take;
                for (int t2 = 0; t2 < take; t2++)
                    fq[w][(fqt + ofs + t2) & (FQCAP - 1)] = start + t2;
                fqt += total;
                start += take;
                cnt -= take;
                __syncwarp();

                while (fqt - fqh >= 32) {
                    int fe = fq[w][(fqh + lane) & (FQCAP - 1)];
                    fqh += 32;
                    float4 pl = __ldg(&g_pplane[fe]);
                    bool kp = fabsf(fmaf(px, pl.x, fmaf(py, pl.y, fmaf(pz, pl.z, pl.w)))) <= sq;
                    unsigned mm = __ballot_sync(0xFFFFFFFFu, kp);
                    if (kp) eq[w][(eqt + __popc(mm & lm)) & (EQCAP - 1)] = fe;
                    eqt += __popc(mm);
                    __syncwarp();

                    while (eqt - eqh >= 32) {
                        int ee = eq[w][(eqh + lane) & (EQCAP - 1)];
                        eqh += 32;
                        bool imp = eval_tri(ee, px, py, pz, bk, bs);
                        if (__ballot_sync(0xFFFFFFFFu, imp)) tighten(bk, sq);
                    }
                    __syncwarp();
                }
            }
        }

        // Drain fine remainder
        {
            int rem = fqt - fqh;
            bool kp = false;
            int fe = 0;
            if (lane < rem) {
                fe = fq[w][(fqh + lane) & (FQCAP - 1)];
                float4 pl = __ldg(&g_pplane[fe]);
                kp = fabsf(fmaf(px, pl.x, fmaf(py, pl.y, fmaf(pz, pl.z, pl.w)))) <= sq;
            }
            unsigned mm = __ballot_sync(0xFFFFFFFFu, kp);
            if (kp) eq[w][(eqt + __popc(mm & lm)) & (EQCAP - 1)] = fe;
            eqt += __popc(mm);
            __syncwarp();
            while (eqt - eqh >= 32) {
                int ee = eq[w][(eqh + lane) & (EQCAP - 1)];
                eqh += 32;
                bool imp = eval_tri(ee, px, py, pz, bk, bs);
                if (__ballot_sync(0xFFFFFFFFu, imp)) tighten(bk, sq);
            }
            rem = eqt - eqh;
            if (lane < rem) {
                int ee = eq[w][(eqh + lane) & (EQCAP - 1)];
                eval_tri(ee, px, py, pz, bk, bs);
            }
            __syncwarp();
        }

        // Warp-reduce (key, sd) lexicographic min — argmin first-index tie-break
        #pragma unroll
        for (int o = 16; o > 0; o >>= 1) {
            unsigned long long ok = __shfl_xor_sync(0xFFFFFFFFu, bk, o);
            float osd = __shfl_xor_sync(0xFFFFFFFFu, bs, o);
            if (ok < bk) { bk = ok; bs = osd; }
        }

        if (lane == 0) {
            float dist2 = __uint_as_float((unsigned)(bk >> 32));
            float dist = sqrtf(fmaxf(dist2, 1e-12f));
            out[pid] = (bs > 0.0f) ? -dist : dist;
        }
    }
}

extern "C" void kernel_launch(void* const* d_in, const int* in_sizes, int n_in,
                              void* d_out, int out_size) {
    const float* points   = (const float*)d_in[0];
    const float* vertices = (const float*)d_in[1];
    const int*   faces    = (const int*)d_in[2];
    float* out = (float*)d_out;

    k1_tris<<<NF / 256, 256>>>(vertices, faces);
    k2_hist<<<NF / 256, 256>>>();
    k3_scan<<<1, 256>>>();
    k4_scatter<<<NF / 256, 256>>>();
    k5_sort<<<NBIN, 256>>>();
    sdf_main<<<NBLK, TPB>>>(points, out);
}

// round 14
// speedup vs baseline: 1.8045x; 1.8045x over previous
#include <cuda_runtime.h>
#include <cuda_bf16.h>
#include <math_constants.h>

#define NV 8192
#define NF 16384
#define NP 16384
#define TPB 128
#define WPB (TPB / 32)
#define QCAP 256
#define NBLK 1036   // ~7 blocks per SM, persistent

// Packed per-triangle data: ax,ay,az, bx,by,bz, cx,cy,cz, nx,ny,nz
__device__ __align__(16) float g_tri[NF * 12];
// Plane cull data: unit normal xyz, w = -dot(a, n_hat). Zero if degenerate.
__device__ float4 g_plane[NF];
// Dynamic work counter (reset each launch in precompute_tris)
__device__ int g_ctr;

// ---------- strict IEEE helpers (bit-stable vs reference) ----------
__device__ __forceinline__ float dot3(float x0, float x1, float x2,
                                      float y0, float y1, float y2) {
    return __fadd_rn(__fadd_rn(__fmul_rn(x0, y0), __fmul_rn(x1, y1)),
                     __fmul_rn(x2, y2));
}
__device__ __forceinline__ float sdiv(float x, float y) {
    return __fdiv_rn(x, (y == 0.0f) ? 1.0f : y);
}

// ---------- kernel 1: triangle precompute (+ work counter reset) ----------
__global__ void precompute_tris(const float* __restrict__ vertices,
                                const int* __restrict__ faces) {
    int f = blockIdx.x * blockDim.x + threadIdx.x;
    if (f == 0) g_ctr = 0;
    if (f >= NF) return;
    int i0 = faces[f * 3 + 0];
    int i1 = faces[f * 3 + 1];
    int i2 = faces[f * 3 + 2];
    float ax = vertices[i0 * 3 + 0], ay = vertices[i0 * 3 + 1], az = vertices[i0 * 3 + 2];
    float bx = vertices[i1 * 3 + 0], by = vertices[i1 * 3 + 1], bz = vertices[i1 * 3 + 2];
    float cx = vertices[i2 * 3 + 0], cy = vertices[i2 * 3 + 1], cz = vertices[i2 * 3 + 2];
    float abx = __fsub_rn(bx, ax), aby = __fsub_rn(by, ay), abz = __fsub_rn(bz, az);
    float acx = __fsub_rn(cx, ax), acy = __fsub_rn(cy, ay), acz = __fsub_rn(cz, az);
    float nx = __fsub_rn(__fmul_rn(aby, acz), __fmul_rn(abz, acy));
    float ny = __fsub_rn(__fmul_rn(abz, acx), __fmul_rn(abx, acz));
    float nz = __fsub_rn(__fmul_rn(abx, acy), __fmul_rn(aby, acx));
    float* t = &g_tri[f * 12];
    t[0] = ax; t[1] = ay; t[2] = az;
    t[3] = bx; t[4] = by; t[5] = bz;
    t[6] = cx; t[7] = cy; t[8] = cz;
    t[9] = nx; t[10] = ny; t[11] = nz;

    float len2 = nx * nx + ny * ny + nz * nz;
    if (len2 > 0.0f) {
        float inv = rsqrtf(len2);
        float ux = nx * inv, uy = ny * inv, uz = nz * inv;
        float d = ax * ux + ay * uy + az * uz;
        g_plane[f] = make_float4(ux, uy, uz, -d);
    } else {
        g_plane[f] = make_float4(0.0f, 0.0f, 0.0f, 0.0f);  // never culled
    }
}

// Evaluate one triangle exactly (bit-identical to reference); update lane best.
__device__ __forceinline__ bool eval_tri(
    int fe, float px, float py, float pz,
    unsigned long long& best_key, float& best_sd)
{
    const float4* tq = reinterpret_cast<const float4*>(&g_tri[fe * 12]);
    float4 q0 = __ldg(&tq[0]);
    float4 q1 = __ldg(&tq[1]);
    float4 q2 = __ldg(&tq[2]);
    float ax = q0.x, ay = q0.y, az = q0.z;
    float bx = q0.w, by = q1.x, bz = q1.y;
    float cx = q1.z, cy = q1.w, cz = q2.x;
    float nx = q2.y, ny = q2.z, nz = q2.w;

    float abx = __fsub_rn(bx, ax), aby = __fsub_rn(by, ay), abz = __fsub_rn(bz, az);
    float acx = __fsub_rn(cx, ax), acy = __fsub_rn(cy, ay), acz = __fsub_rn(cz, az);
    float apx = __fsub_rn(px, ax), apy = __fsub_rn(py, ay), apz = __fsub_rn(pz, az);
    float bpx = __fsub_rn(px, bx), bpy = __fsub_rn(py, by), bpz = __fsub_rn(pz, bz);
    float cpx = __fsub_rn(px, cx), cpy = __fsub_rn(py, cy), cpz = __fsub_rn(pz, cz);

    float d1 = dot3(abx, aby, abz, apx, apy, apz);
    float d2 = dot3(acx, acy, acz, apx, apy, apz);
    float d3 = dot3(abx, aby, abz, bpx, bpy, bpz);
    float d4 = dot3(acx, acy, acz, bpx, bpy, bpz);
    float d5 = dot3(abx, aby, abz, cpx, cpy, cpz);
    float d6 = dot3(acx, acy, acz, cpx, cpy, cpz);

    float va = __fsub_rn(__fmul_rn(d3, d6), __fmul_rn(d5, d4));
    float vb = __fsub_rn(__fmul_rn(d5, d2), __fmul_rn(d1, d6));
    float vc = __fsub_rn(__fmul_rn(d1, d4), __fmul_rn(d3, d2));
    float denom = __fadd_rn(__fadd_rn(va, vb), vc);
    float v = sdiv(vb, denom);
    float w = sdiv(vc, denom);

    float e43 = __fsub_rn(d4, d3);
    float e56 = __fsub_rn(d5, d6);
    float t_bc = sdiv(e43, __fadd_rn(e43, e56));
    if (va <= 0.0f && e43 >= 0.0f && e56 >= 0.0f) {
        v = __fsub_rn(1.0f, t_bc); w = t_bc;
    }
    float t_ac = sdiv(d2, __fsub_rn(d2, d6));
    if (vb <= 0.0f && d2 >= 0.0f && d6 <= 0.0f) { v = 0.0f; w = t_ac; }
    float t_ab = sdiv(d1, __fsub_rn(d1, d3));
    if (vc <= 0.0f && d1 >= 0.0f && d3 <= 0.0f) { v = t_ab; w = 0.0f; }
    if (d6 >= 0.0f && d5 <= d6) { v = 0.0f; w = 1.0f; }
    if (d3 >= 0.0f && d4 <= d3) { v = 1.0f; w = 0.0f; }
    if (d1 <= 0.0f && d2 <= 0.0f) { v = 0.0f; w = 0.0f; }

    float clx = __fadd_rn(__fadd_rn(ax, __fmul_rn(v, abx)), __fmul_rn(w, acx));
    float cly = __fadd_rn(__fadd_rn(ay, __fmul_rn(v, aby)), __fmul_rn(w, acy));
    float clz = __fadd_rn(__fadd_rn(az, __fmul_rn(v, abz)), __fmul_rn(w, acz));
    float dx = __fsub_rn(px, clx);
    float dy = __fsub_rn(py, cly);
    float dz = __fsub_rn(pz, clz);
    float dist2 = dot3(dx, dy, dz, dx, dy, dz);

    unsigned long long key =
        ((unsigned long long)__float_as_uint(dist2) << 32) | (unsigned)fe;
    if (key < best_key) {
        best_key = key;
        best_sd = dot3(dx, dy, dz, nx, ny, nz);
        return true;
    }
    return false;
}

// ---------- kernel 2: persistent warps, exact-eval seed, 4-wide cull ---------
__global__ void __launch_bounds__(TPB) sdf_main(const float* __restrict__ points,
                                                float* __restrict__ out) {
    __shared__ int queue[WPB][QCAP];

    int warp_in_blk = threadIdx.x / 32;
    int lane = threadIdx.x % 32;
    unsigned lanemask = (1u << lane) - 1u;

    for (;;) {
        int pid;
        if (lane == 0) pid = atomicAdd(&g_ctr, 1);
        pid = __shfl_sync(0xFFFFFFFFu, pid, 0);
        if (pid >= NP) break;

        float px = points[pid * 3 + 0];
        float py = points[pid * 3 + 1];
        float pz = points[pid * 3 + 2];

        // Seed: per-lane argmin over 32 strided vertex-a distances, then ONE
        // exact eval batch of the 32 argmin faces. sq collapses to near-true
        // min immediately; extra evals only add min-candidates (bit-safe).
        float ub2 = CUDART_INF_F;
        int af = lane;
        #pragma unroll 4
        for (int i = 0; i < 32; i++) {
            int f = i * 32 + lane;
            const float4* tq = reinterpret_cast<const float4*>(&g_tri[f * 12]);
            float4 q0 = __ldg(&tq[0]);
            float dx = px - q0.x, dy = py - q0.y, dz = pz - q0.z;
            float d2 = fmaf(dx, dx, fmaf(dy, dy, dz * dz));
            if (d2 < ub2) { ub2 = d2; af = f; }
        }
        unsigned long long best_key = 0xFFFFFFFFFFFFFFFFull;
        float best_sd = 0.0f;
        eval_tri(af, px, py, pz, best_key, best_sd);
        float bd2 = __uint_as_float((unsigned)(best_key >> 32));
        #pragma unroll
        for (int o = 16; o > 0; o >>= 1)
            bd2 = fminf(bd2, __shfl_xor_sync(0xFFFFFFFFu, bd2, o));
        float sq = fmaf(sqrtf(bd2), 1.001f, 1e-6f);

        int qn = 0, qhead = 0;

        // Prime the prefetch pipeline
        float4 pl0 = __ldg(&g_plane[lane]);
        float4 pl1 = __ldg(&g_plane[lane + 32]);
        float4 pl2 = __ldg(&g_plane[lane + 64]);
        float4 pl3 = __ldg(&g_plane[lane + 96]);

        for (int chunk = 0; chunk < NF; chunk += 128) {
            float pd0 = fabsf(fmaf(px, pl0.x, fmaf(py, pl0.y, fmaf(pz, pl0.z, pl0.w))));
            float pd1 = fabsf(fmaf(px, pl1.x, fmaf(py, pl1.y, fmaf(pz, pl1.z, pl1.w))));
            float pd2 = fabsf(fmaf(px, pl2.x, fmaf(py, pl2.y, fmaf(pz, pl2.z, pl2.w))));
            float pd3 = fabsf(fmaf(px, pl3.x, fmaf(py, pl3.y, fmaf(pz, pl3.z, pl3.w))));
            bool k0 = (pd0 <= sq);
            bool k1 = (pd1 <= sq);
            bool k2 = (pd2 <= sq);
            bool k3 = (pd3 <= sq);

            // Prefetch next chunk's planes
            int nxt = chunk + 128;
            if (nxt < NF) {
                pl0 = __ldg(&g_plane[nxt + lane]);
                pl1 = __ldg(&g_plane[nxt + lane + 32]);
                pl2 = __ldg(&g_plane[nxt + lane + 64]);
                pl3 = __ldg(&g_plane[nxt + lane + 96]);
            }

            // Fast path: most chunks have zero survivors warp-wide
            if (!__ballot_sync(0xFFFFFFFFu, k0 | k1 | k2 | k3)) continue;

            unsigned m0 = __ballot_sync(0xFFFFFFFFu, k0);
            unsigned m1 = __ballot_sync(0xFFFFFFFFu, k1);
            unsigned m2 = __ballot_sync(0xFFFFFFFFu, k2);
            unsigned m3 = __ballot_sync(0xFFFFFFFFu, k3);
            int n0 = __popc(m0);
            int n1 = __popc(m1);
            int n2 = __popc(m2);
            if (k0) queue[warp_in_blk][(qhead + qn + __popc(m0 & lanemask)) & (QCAP - 1)] = chunk + lane;
            if (k1) queue[warp_in_blk][(qhead + qn + n0 + __popc(m1 & lanemask)) & (QCAP - 1)] = chunk + lane + 32;
            if (k2) queue[warp_in_blk][(qhead + qn + n0 + n1 + __popc(m2 & lanemask)) & (QCAP - 1)] = chunk + lane + 64;
            if (k3) queue[warp_in_blk][(qhead + qn + n0 + n1 + n2 + __popc(m3 & lanemask)) & (QCAP - 1)] = chunk + lane + 96;
            qn += n0 + n1 + n2 + __popc(m3);
            __syncwarp();

            while (qn >= 32) {
                int fe = queue[warp_in_blk][(qhead + lane) & (QCAP - 1)];
                qhead += 32;
                qn -= 32;
                bool improved = eval_tri(fe, px, py, pz, best_key, best_sd);
                if (__ballot_sync(0xFFFFFFFFu, improved)) {
                    float b2 = __uint_as_float((unsigned)(best_key >> 32));
                    #pragma unroll
                    for (int o = 16; o > 0; o >>= 1)
                        b2 = fminf(b2, __shfl_xor_sync(0xFFFFFFFFu, b2, o));
                    sq = fminf(sq, fmaf(sqrtf(b2), 1.001f, 1e-6f));
                }
            }
            __syncwarp();
        }

        // Drain remaining queued survivors
        if (lane < qn) {
            int fe = queue[warp_in_blk][(qhead + lane) & (QCAP - 1)];
            eval_tri(fe, px, py, pz, best_key, best_sd);
        }
        __syncwarp();

        // Warp-reduce (key, sd) lexicographic min — argmin first-index tie-break
        #pragma unroll
        for (int o = 16; o > 0; o >>= 1) {
            unsigned long long ok = __shfl_xor_sync(0xFFFFFFFFu, best_key, o);
            float osd = __shfl_xor_sync(0xFFFFFFFFu, best_sd, o);
            if (ok < best_key) { best_key = ok; best_sd = osd; }
        }

        if (lane == 0) {
            float dist2 = __uint_as_float((unsigned)(best_key >> 32));
            float dist = sqrtf(fmaxf(dist2, 1e-12f));
            out[pid] = (best_sd > 0.0f) ? -dist : dist;
        }
    }
}

extern "C" void kernel_launch(void* const* d_in, const int* in_sizes, int n_in,
                              void* d_out, int out_size) {
    const float* points   = (const float*)d_in[0];
    const float* vertices = (const float*)d_in[1];
    const int*   faces    = (const int*)d_in[2];
    float* out = (float*)d_out;

    precompute_tris<<<(NF + 255) / 256, 256>>>(vertices, faces);
    sdf_main<<<NBLK, TPB>>>(points, out);
}